// round 14
// baseline (speedup 1.0000x reference)
#include <cuda_runtime.h>
#include <math.h>
#include <math_constants.h>

// Problem constants (shapes fixed by setup_inputs)
#define B 16
#define C 1024
#define D 768
#define KH 306          // int((C-1) * 0.3)
#define KR 717          // (C-1) - KH
#define TAUF 0.1f
#define GG 16           // anchors per GEMM group
#define KSPLIT 6        // k-split factor
#define KQ 128          // D / KSPLIT
#define GEMM_BLOCKS 312
#define SEL_BLOCKS 256

// ---- device scratch (module globals; no runtime allocation) ----
__device__ float          g_pT[D * C];                   // protos transposed [k][c] (unnormalized)
__device__ float          g_pinv[C];                     // 1/max(||p_c||,eps)
__device__ float          g_sims[B * C * KSPLIT * C];    // partial sims: [listpos][q][C]
__device__ float          g_lossd[B * C];                // per-positive loss / poscnt, dense
__device__ unsigned char  g_mask[B * C];                 // bit0 = rand-negative, bit1 = positive
__device__ float          g_poscnt[B];                   // clip(count,1)
__device__ int            g_cnt[B];                      // positives per batch
__device__ int            g_list[B * 1024];              // column index of each positive, per batch
__device__ unsigned       g_done;                        // select-block completion counter

// packed f32x2 FMA
__device__ __forceinline__ unsigned long long ffma2(unsigned long long a,
                                                    unsigned long long b,
                                                    unsigned long long c) {
    unsigned long long d;
    asm("fma.rn.f32x2 %0, %1, %2, %3;" : "=l"(d) : "l"(a), "l"(b), "l"(c));
    return d;
}

// named barrier for a 256-thread group
__device__ __forceinline__ void gbar(int id) {
    asm volatile("bar.sync %0, 256;" :: "r"(id) : "memory");
}

// ===========================================================================
// Block-wide (1024-thread) radix select: Ksel-th largest among keys (0=excl).
__device__ __forceinline__ void radix_select_desc(
    unsigned key, int Ksel,
    unsigned* hist, unsigned* S, unsigned* wtot,
    unsigned* sh_prefix, unsigned* sh_rem,
    int tid, int lane)
{
    if (tid == 0) { *sh_prefix = 0u; *sh_rem = (unsigned)Ksel; }
    __syncthreads();
#pragma unroll
    for (int byte = 3; byte >= 0; byte--) {
        int shift = byte * 8;
        if (tid < 256) hist[tid] = 0u;
        __syncthreads();
        unsigned pfx = *sh_prefix;
        bool match = (byte == 3) || ((key >> (shift + 8)) == (pfx >> (shift + 8)));
        if (match && key != 0u) atomicAdd(&hist[(key >> shift) & 255u], 1u);
        __syncthreads();
        if (tid < 256) {
            unsigned v = hist[tid];
#pragma unroll
            for (int d = 1; d < 32; d <<= 1) {
                unsigned t2 = __shfl_down_sync(0xFFFFFFFFu, v, d);
                if (lane + d < 32) v += t2;
            }
            S[tid] = v;
            if (lane == 0) wtot[tid >> 5] = v;
        }
        __syncthreads();
        unsigned remloc = *sh_rem;
        if (tid < 256) {
            unsigned ws = 0;
            for (int w = (tid >> 5) + 1; w < 8; w++) ws += wtot[w];
            S[tid] += ws;
        }
        __syncthreads();
        if (tid < 256) {
            unsigned st = S[tid];
            unsigned snext = (tid == 255) ? 0u : S[tid + 1];
            if (st >= remloc && snext < remloc) {
                *sh_prefix = pfx | ((unsigned)tid << shift);
                *sh_rem = remloc - snext;
            }
        }
        __syncthreads();
    }
}

// ===========================================================================
// Group (256-thread, 4 keys/thread) radix select with named barrier `barid`.
__device__ __forceinline__ void radix4(
    const unsigned key[4], int Ksel,
    unsigned* hist, unsigned* S, unsigned* wtot,
    volatile unsigned* sh_prefix, volatile unsigned* sh_rem,
    int gtid, int lane, int wg, int barid)
{
    if (gtid == 0) { *sh_prefix = 0u; *sh_rem = (unsigned)Ksel; }
    gbar(barid);
#pragma unroll
    for (int byte = 3; byte >= 0; byte--) {
        int shift = byte * 8;
        hist[gtid] = 0u;
        gbar(barid);
        unsigned pfx = *sh_prefix;
#pragma unroll
        for (int x = 0; x < 4; x++) {
            bool match = (byte == 3) || ((key[x] >> (shift + 8)) == (pfx >> (shift + 8)));
            if (match && key[x] != 0u) atomicAdd(&hist[(key[x] >> shift) & 255u], 1u);
        }
        gbar(barid);
        unsigned v = hist[gtid];
#pragma unroll
        for (int d = 1; d < 32; d <<= 1) {
            unsigned t2 = __shfl_down_sync(0xFFFFFFFFu, v, d);
            if (lane + d < 32) v += t2;
        }
        if (lane == 0) wtot[wg] = v;
        gbar(barid);
        unsigned remloc = *sh_rem;
        unsigned ws = 0;
        for (int w = wg + 1; w < 8; w++) ws += wtot[w];
        unsigned st = v + ws;            // suffix sum from this bin
        S[gtid] = st;
        gbar(barid);
        unsigned snext = (gtid == 255) ? 0u : S[gtid + 1];
        if (st >= remloc && snext < remloc) {
            *sh_prefix = pfx | ((unsigned)gtid << shift);
            *sh_rem = remloc - snext;
        }
        gbar(barid);
    }
}

// ===========================================================================
// prep (1024 threads/block, 256 blocks -> single wave):
//   [0,192)   : 32(C)x128(D) tile transpose p -> g_pT (float4 both ways)
//   [192,224) : proto row norms -> g_pinv (warp per row)
//   [224,240) : rand-negative + positive mask byte per batch elem
//   [240,256) : rank-based positive compaction (+ g_done reset)
__global__ void __launch_bounds__(1024) k_prep(const float* __restrict__ p,
                                               const int* __restrict__ tg,
                                               const float* __restrict__ rs) {
    __shared__ float tile[32][133];
    __shared__ unsigned hist[256];
    __shared__ unsigned S[256];
    __shared__ unsigned wtot[32];
    __shared__ unsigned sh_prefix, sh_rem;
    __shared__ int s_ts;

    int tid = threadIdx.x;
    int lane = tid & 31, wid = tid >> 5;
    int blk = blockIdx.x;

    if (blk < 192) {
        // ---- transpose 32 proto rows x 128 features ----
        int tx = blk % 32;           // C tile (32 rows of p)
        int ty = blk / 32;           // D tile (128 cols of p)
        // load: warp w reads p-row tx*32+w, cols ty*128 + lane*4
        float4 v = *(const float4*)(p + (size_t)(tx * 32 + wid) * D + ty * 128 + lane * 4);
        tile[wid][lane * 4 + 0] = v.x;
        tile[wid][lane * 4 + 1] = v.y;
        tile[wid][lane * 4 + 2] = v.z;
        tile[wid][lane * 4 + 3] = v.w;
        __syncthreads();
        // store: thread handles output row r = tid>>3 (feature), 4 cols
        int r = tid >> 3;
        int cc = (tid & 7) * 4;
        float4 o;
        o.x = tile[cc + 0][r];
        o.y = tile[cc + 1][r];
        o.z = tile[cc + 2][r];
        o.w = tile[cc + 3][r];
        *(float4*)(g_pT + (size_t)(ty * 128 + r) * C + tx * 32 + cc) = o;
        return;
    }
    if (blk < 224) {
        int j = (blk - 192) * 32 + wid;
        const float* pr = p + (size_t)j * D;
        float ss = 0.f;
#pragma unroll
        for (int t = 0; t < 24; t++) { float v = pr[lane + 32 * t]; ss += v * v; }
#pragma unroll
        for (int d = 16; d > 0; d >>= 1) ss += __shfl_xor_sync(0xFFFFFFFFu, ss, d);
        if (lane == 0) g_pinv[j] = 1.f / fmaxf(sqrtf(ss), 1e-12f);
        return;
    }

    // ---- dtype probe on this batch's word window [b*1024, b*1024+1024) ----
    int b = (blk < 240) ? (blk - 224) : (blk - 240);
    int w0 = tg[b * 1024 + tid];                       // word view; in-bounds either dtype
    bool oddnz = ((tid & 1) != 0) && (w0 != 0);
    unsigned ob = __ballot_sync(0xFFFFFFFFu, oddnz);
    if (lane == 0) wtot[wid] = ob ? 1u : 0u;
    __syncthreads();
    if (tid == 0) {
        unsigned fl = 0;
        for (int w = 0; w < 32; w++) fl |= wtot[w];
        s_ts = fl ? 1 : 2;                             // 1=int32, 2=int64
    }
    __syncthreads();
    int ts = s_ts;
    bool posc = (ts == 1) ? (w0 != 0) : (tg[(b * C + tid) * 2] != 0);
    __syncthreads();

    if (blk < 240) {
        // ---- rand-negative membership + mask byte ----
        float r = rs[b * C + tid];
        unsigned key = posc ? 0u : (__float_as_uint(r) + 1u);   // monotone, >0

        radix_select_desc(key, KR, hist, S, wtot, &sh_prefix, &sh_rem, tid, lane);
        unsigned T = sh_prefix;
        unsigned remf = sh_rem;

        // tie resolution by lowest index (matches jax.lax.top_k stability)
        bool eq = (key == T) && (key != 0u);
        unsigned eb = __ballot_sync(0xFFFFFFFFu, eq);
        if (lane == 0) wtot[wid] = (unsigned)__popc(eb);
        __syncthreads();
        unsigned off = 0;
        for (int w = 0; w < wid; w++) off += wtot[w];
        unsigned rank = off + (unsigned)__popc(eb & ((1u << lane) - 1u));
        bool in = (key != 0u) && ((key > T) || (eq && rank < remf));
        g_mask[b * C + tid] = (unsigned char)((posc ? 2 : 0) | (in ? 1 : 0));
    } else {
        // ---- rank-based compaction ----
        unsigned bal = __ballot_sync(0xFFFFFFFFu, posc);
        if (lane == 0) wtot[wid] = (unsigned)__popc(bal);
        __syncthreads();
        unsigned off = 0;
        for (int w = 0; w < wid; w++) off += wtot[w];
        unsigned rank = off + (unsigned)__popc(bal & ((1u << lane) - 1u));
        if (posc) g_list[b * 1024 + rank] = tid;
        if (tid == 0) {
            unsigned cnt = 0;
            for (int w = 0; w < 32; w++) cnt += wtot[w];
            g_cnt[b] = (int)cnt;
            g_poscnt[b] = (float)(cnt > 0 ? cnt : 1u);
            if (b == 0) g_done = 0u;                   // reset tail counter each launch
        }
    }
}

// ===========================================================================
// GEMM: items = (anchor group of GG) x (k-sixth). 256 threads, 4 cols/thread,
// f rows pre-duplicated {v,v} in smem, inner loop = LDS.64-bcast + FFMA2.
__global__ void __launch_bounds__(256) k_gemm(const float* __restrict__ f) {
    __shared__ unsigned long long f2_s[GG][KQ];   // 16,384 B
    __shared__ int s_anchor[GG];
    __shared__ int s_pfx[17];

    int tid = threadIdx.x;
    int wid = tid >> 5, lane = tid & 31;

    if (tid == 0) {
        int acc = 0;
        for (int b = 0; b < B; b++) { s_pfx[b] = acc; acc += g_cnt[b]; }
        s_pfx[16] = acc;
    }
    __syncthreads();
    int npos = s_pfx[16];
    int ng = (npos + GG - 1) / GG;
    int nitems = ng * KSPLIT;

    for (int item = blockIdx.x; item < nitems; item += GEMM_BLOCKS) {
        int grp = item / KSPLIT;
        int sixth = item - grp * KSPLIT;
        __syncthreads();   // previous iter's f2_s reads done
        if (tid < GG) {
            int idx = grp * GG + tid;
            int aa = -1;
            if (idx < npos) {
                int bb = 0;
                while (bb < 15 && idx >= s_pfx[bb + 1]) bb++;
                aa = bb * C + g_list[bb * 1024 + (idx - s_pfx[bb])];
            }
            s_anchor[tid] = aa;
        }
        __syncthreads();

        for (int u = wid; u < GG; u += 8) {
            int a = s_anchor[u];
            float vs[24];
            float ss = 0.f;
            if (a >= 0) {
                const float* fr = f + (size_t)a * D;
#pragma unroll
                for (int t = 0; t < 24; t++) {
                    float v = fr[lane + 32 * t];
                    vs[t] = v; ss += v * v;
                }
            } else {
#pragma unroll
                for (int t = 0; t < 24; t++) vs[t] = 0.f;
            }
#pragma unroll
            for (int d = 16; d > 0; d >>= 1) ss += __shfl_xor_sync(0xFFFFFFFFu, ss, d);
            float inv = (1.f / fmaxf(sqrtf(ss), 1e-12f)) * (1.f / TAUF);
#pragma unroll
            for (int t = 0; t < 4; t++) {
                unsigned vb = __float_as_uint(vs[sixth * 4 + t] * inv);
                f2_s[u][lane + 32 * t] = ((unsigned long long)vb << 32) | vb;
            }
        }
        __syncthreads();

        int col = 4 * tid;
        const float* pc = g_pT + (size_t)sixth * KQ * C + col;
        unsigned long long accA[GG], accB[GG];
#pragma unroll
        for (int u = 0; u < GG; u++) { accA[u] = 0ull; accB[u] = 0ull; }

#pragma unroll 2
        for (int k = 0; k < KQ; k++) {
            union { float4 v; unsigned long long ll[2]; } pu;
            pu.v = *(const float4*)(pc + (size_t)k * C);
#pragma unroll
            for (int u = 0; u < GG; u++) {
                unsigned long long fv = f2_s[u][k];
                accA[u] = ffma2(fv, pu.ll[0], accA[u]);
                accB[u] = ffma2(fv, pu.ll[1], accB[u]);
            }
        }

        float4 pinv = *(const float4*)(g_pinv + col);
        int base = grp * GG;
#pragma unroll
        for (int u = 0; u < GG; u++) {
            if (base + u < npos) {
                float2 a2 = *(float2*)&accA[u];
                float2 b2 = *(float2*)&accB[u];
                float4 o;
                o.x = a2.x * pinv.x; o.y = a2.y * pinv.y;
                o.z = b2.x * pinv.z; o.w = b2.y * pinv.w;
                *(float4*)&g_sims[(size_t)(base + u) * (KSPLIT * 1024) +
                                  sixth * 1024 + col] = o;
            }
        }
    }
}

// ===========================================================================
// select+loss+final: 4 independent 256-thread groups per block; per-anchor
// radix select; losses stored pre-divided by poscnt; last block to finish
// performs the flat deterministic sum and writes the scalar output.
__global__ void __launch_bounds__(1024) k_select(float* __restrict__ out) {
    __shared__ unsigned hist[4][256];
    __shared__ unsigned S[4][256];
    __shared__ unsigned wtot[4][8];
    __shared__ unsigned sh_prefix[4], sh_rem[4];
    __shared__ unsigned u_red[4][8];
    __shared__ float    f_red[4][8];
    __shared__ float    s_vT[4], s_possim[4];
    __shared__ int      s_pfx[17];
    __shared__ int      s_last;
    __shared__ float    s_fin[32];

    int tid = threadIdx.x;
    int lane = tid & 31;
    int g = tid >> 8;            // group 0..3
    int gtid = tid & 255;
    int wg = (tid >> 5) & 7;     // warp within group
    int barid = g + 1;

    if (tid == 0) {
        int acc = 0;
        for (int b = 0; b < B; b++) { s_pfx[b] = acc; acc += g_cnt[b]; }
        s_pfx[16] = acc;
    }
    __syncthreads();
    int npos = s_pfx[16];

    for (int i = blockIdx.x * 4 + g; i < npos; i += SEL_BLOCKS * 4) {
        // anchor decode (redundant per thread; no sync needed)
        int bb = 0;
        while (bb < 15 && i >= s_pfx[bb + 1]) bb++;
        int c = g_list[bb * 1024 + (i - s_pfx[bb])];

        // load 6 partials per column, fixed summation order
        const float* sp = g_sims + (size_t)i * (KSPLIT * 1024) + 4 * gtid;
        float4 q0 = *(const float4*)(sp);
        float4 q1 = *(const float4*)(sp + 1024);
        float4 q2 = *(const float4*)(sp + 2048);
        float4 q3 = *(const float4*)(sp + 3072);
        float4 q4 = *(const float4*)(sp + 4096);
        float4 q5 = *(const float4*)(sp + 5120);
        float sim[4];
        sim[0] = ((q0.x + q1.x) + (q2.x + q3.x)) + (q4.x + q5.x);
        sim[1] = ((q0.y + q1.y) + (q2.y + q3.y)) + (q4.y + q5.y);
        sim[2] = ((q0.z + q1.z) + (q2.z + q3.z)) + (q4.z + q5.z);
        sim[3] = ((q0.w + q1.w) + (q2.w + q3.w)) + (q4.w + q5.w);

        uchar4 mk4 = *(const uchar4*)(g_mask + bb * C + 4 * gtid);
        unsigned char mk[4] = {mk4.x, mk4.y, mk4.z, mk4.w};

        unsigned key[4];
#pragma unroll
        for (int x = 0; x < 4; x++) {
            unsigned bits = __float_as_uint(sim[x]);
            unsigned flip = bits ^ ((bits & 0x80000000u) ? 0xFFFFFFFFu : 0x80000000u);
            key[x] = (mk[x] & 2) ? 0u : flip;
        }
        if ((c >> 2) == gtid) s_possim[g] = sim[c & 3];

        // max negative key -> m
        unsigned mx = max(max(key[0], key[1]), max(key[2], key[3]));
#pragma unroll
        for (int d = 16; d > 0; d >>= 1) mx = max(mx, __shfl_xor_sync(0xFFFFFFFFu, mx, d));
        if (lane == 0) u_red[g][wg] = mx;
        gbar(barid);
        unsigned maxkey = u_red[g][0];
#pragma unroll
        for (int w = 1; w < 8; w++) maxkey = max(maxkey, u_red[g][w]);
        unsigned mbits = (maxkey & 0x80000000u) ? (maxkey ^ 0x80000000u) : ~maxkey;
        float m = __uint_as_float(mbits);

        radix4(key, KH, hist[g], S[g], wtot[g], &sh_prefix[g], &sh_rem[g],
               gtid, lane, wg, barid);
        unsigned T = sh_prefix[g];
        unsigned remf = sh_rem[g];

        float contrib = 0.f;
#pragma unroll
        for (int x = 0; x < 4; x++) {
            float e = expf(sim[x] - m);
            if (key[x] > T) contrib += e;
            if (key[x] == T && key[x] != 0u) s_vT[g] = sim[x];  // equal keys = equal values
            if (mk[x] & 1) contrib += e;
        }
#pragma unroll
        for (int d = 16; d > 0; d >>= 1) contrib += __shfl_xor_sync(0xFFFFFFFFu, contrib, d);
        if (lane == 0) f_red[g][wg] = contrib;
        gbar(barid);
        if (gtid == 0) {
            float tot = 0.f;
            for (int w = 0; w < 8; w++) tot += f_red[g][w];
            tot += (float)remf * expf(s_vT[g] - m);
            float lse = m + logf(tot);
            float x = lse - s_possim[g];
            float loss = fmaxf(x, 0.f) + log1pf(expf(-fabsf(x)));
            g_lossd[i] = loss / g_poscnt[bb];          // pre-normalized
        }
        gbar(barid);   // close iteration: protect s_possim / s_vT / smem reuse
    }

    // ---- fused final reduction: last block to arrive sums everything ----
    __syncthreads();
    if (tid == 0) {
        __threadfence();
        unsigned r = atomicAdd(&g_done, 1u);
        s_last = (r == SEL_BLOCKS - 1) ? 1 : 0;
    }
    __syncthreads();
    if (s_last) {
        float ps = 0.f;
        for (int j = tid; j < npos; j += 1024) ps += g_lossd[j];
#pragma unroll
        for (int d = 16; d > 0; d >>= 1) ps += __shfl_xor_sync(0xFFFFFFFFu, ps, d);
        if (lane == 0) s_fin[tid >> 5] = ps;
        __syncthreads();
        if (tid < 32) {
            float t = s_fin[tid];
#pragma unroll
            for (int d = 16; d > 0; d >>= 1) t += __shfl_xor_sync(0xFFFFFFFFu, t, d);
            if (tid == 0) out[0] = t / (float)B;
        }
    }
}

// ===========================================================================
extern "C" void kernel_launch(void* const* d_in, const int* in_sizes, int n_in,
                              void* d_out, int out_size) {
    const float* f  = (const float*)d_in[0];   // (B,C,D) fp32
    const float* p  = (const float*)d_in[1];   // (C,D)   fp32
    const int*   tg = (const int*)d_in[2];     // (B,C)   int32 (or int64; self-probed)
    const float* rs = (const float*)d_in[3];   // (B,C)   fp32
    float* out = (float*)d_out;

    k_prep<<<256, 1024>>>(p, tg, rs);
    k_gemm<<<GEMM_BLOCKS, 256>>>(f);
    k_select<<<SEL_BLOCKS, 1024>>>(out);
}

// round 16
// speedup vs baseline: 1.0826x; 1.0826x over previous
#include <cuda_runtime.h>
#include <math.h>
#include <math_constants.h>

// Problem constants (shapes fixed by setup_inputs)
#define B 16
#define C 1024
#define D 768
#define KH 306          // int((C-1) * 0.3)
#define KR 717          // (C-1) - KH
#define TAUF 0.1f
#define GG 12           // anchors per GEMM group
#define KSPLIT 4        // k-split factor
#define KQ 192          // D / KSPLIT
#define GEMM_BLOCKS 276
#define SEL_BLOCKS 256

// ---- device scratch (module globals; no runtime allocation) ----
__device__ float          g_pT[D * C];                   // protos transposed [k][c] (unnormalized)
__device__ float          g_pinv[C];                     // 1/max(||p_c||,eps)
__device__ float          g_sims[B * C * KSPLIT * C];    // partial sims: [listpos][q][C]
__device__ float          g_lossd[B * C];                // per-positive loss / poscnt, dense
__device__ unsigned char  g_mask[B * C];                 // bit0 = rand-negative, bit1 = positive
__device__ float          g_poscnt[B];                   // clip(count,1)
__device__ int            g_cnt[B];                      // positives per batch
__device__ int            g_list[B * 1024];              // column index of each positive, per batch
__device__ unsigned       g_done;                        // select-block completion counter

// packed f32x2 FMA
__device__ __forceinline__ unsigned long long ffma2(unsigned long long a,
                                                    unsigned long long b,
                                                    unsigned long long c) {
    unsigned long long d;
    asm("fma.rn.f32x2 %0, %1, %2, %3;" : "=l"(d) : "l"(a), "l"(b), "l"(c));
    return d;
}

// named barrier for a 256-thread group
__device__ __forceinline__ void gbar(int id) {
    asm volatile("bar.sync %0, 256;" :: "r"(id) : "memory");
}

// ===========================================================================
// Block-wide (1024-thread) radix select: Ksel-th largest among keys (0=excl).
__device__ __forceinline__ void radix_select_desc(
    unsigned key, int Ksel,
    unsigned* hist, unsigned* S, unsigned* wtot,
    unsigned* sh_prefix, unsigned* sh_rem,
    int tid, int lane)
{
    if (tid == 0) { *sh_prefix = 0u; *sh_rem = (unsigned)Ksel; }
    __syncthreads();
#pragma unroll
    for (int byte = 3; byte >= 0; byte--) {
        int shift = byte * 8;
        if (tid < 256) hist[tid] = 0u;
        __syncthreads();
        unsigned pfx = *sh_prefix;
        bool match = (byte == 3) || ((key >> (shift + 8)) == (pfx >> (shift + 8)));
        if (match && key != 0u) atomicAdd(&hist[(key >> shift) & 255u], 1u);
        __syncthreads();
        if (tid < 256) {
            unsigned v = hist[tid];
#pragma unroll
            for (int d = 1; d < 32; d <<= 1) {
                unsigned t2 = __shfl_down_sync(0xFFFFFFFFu, v, d);
                if (lane + d < 32) v += t2;
            }
            S[tid] = v;
            if (lane == 0) wtot[tid >> 5] = v;
        }
        __syncthreads();
        unsigned remloc = *sh_rem;
        if (tid < 256) {
            unsigned ws = 0;
            for (int w = (tid >> 5) + 1; w < 8; w++) ws += wtot[w];
            S[tid] += ws;
        }
        __syncthreads();
        if (tid < 256) {
            unsigned st = S[tid];
            unsigned snext = (tid == 255) ? 0u : S[tid + 1];
            if (st >= remloc && snext < remloc) {
                *sh_prefix = pfx | ((unsigned)tid << shift);
                *sh_rem = remloc - snext;
            }
        }
        __syncthreads();
    }
}

// ===========================================================================
// Group (256-thread, 4 keys/thread) radix select with named barrier `barid`.
__device__ __forceinline__ void radix4(
    const unsigned key[4], int Ksel,
    unsigned* hist, unsigned* S, unsigned* wtot,
    volatile unsigned* sh_prefix, volatile unsigned* sh_rem,
    int gtid, int lane, int wg, int barid)
{
    if (gtid == 0) { *sh_prefix = 0u; *sh_rem = (unsigned)Ksel; }
    gbar(barid);
#pragma unroll
    for (int byte = 3; byte >= 0; byte--) {
        int shift = byte * 8;
        hist[gtid] = 0u;
        gbar(barid);
        unsigned pfx = *sh_prefix;
#pragma unroll
        for (int x = 0; x < 4; x++) {
            bool match = (byte == 3) || ((key[x] >> (shift + 8)) == (pfx >> (shift + 8)));
            if (match && key[x] != 0u) atomicAdd(&hist[(key[x] >> shift) & 255u], 1u);
        }
        gbar(barid);
        unsigned v = hist[gtid];
#pragma unroll
        for (int d = 1; d < 32; d <<= 1) {
            unsigned t2 = __shfl_down_sync(0xFFFFFFFFu, v, d);
            if (lane + d < 32) v += t2;
        }
        if (lane == 0) wtot[wg] = v;
        gbar(barid);
        unsigned remloc = *sh_rem;
        unsigned ws = 0;
        for (int w = wg + 1; w < 8; w++) ws += wtot[w];
        unsigned st = v + ws;            // suffix sum from this bin
        S[gtid] = st;
        gbar(barid);
        unsigned snext = (gtid == 255) ? 0u : S[gtid + 1];
        if (st >= remloc && snext < remloc) {
            *sh_prefix = pfx | ((unsigned)gtid << shift);
            *sh_rem = remloc - snext;
        }
        gbar(barid);
    }
}

// ===========================================================================
// prep (1024 threads/block, 256 blocks -> single wave):
//   [0,192)   : 32(C)x128(D) tile transpose p -> g_pT (float4 both ways)
//   [192,224) : proto row norms -> g_pinv (warp per row)
//   [224,240) : rand-negative + positive mask byte per batch elem
//   [240,256) : rank-based positive compaction (+ g_done reset)
__global__ void __launch_bounds__(1024) k_prep(const float* __restrict__ p,
                                               const int* __restrict__ tg,
                                               const float* __restrict__ rs) {
    __shared__ float tile[32][133];
    __shared__ unsigned hist[256];
    __shared__ unsigned S[256];
    __shared__ unsigned wtot[32];
    __shared__ unsigned sh_prefix, sh_rem;
    __shared__ int s_ts;

    int tid = threadIdx.x;
    int lane = tid & 31, wid = tid >> 5;
    int blk = blockIdx.x;

    if (blk < 192) {
        // ---- transpose 32 proto rows x 128 features ----
        int tx = blk % 32;           // C tile (32 rows of p)
        int ty = blk / 32;           // D tile (128 cols of p)
        float4 v = *(const float4*)(p + (size_t)(tx * 32 + wid) * D + ty * 128 + lane * 4);
        tile[wid][lane * 4 + 0] = v.x;
        tile[wid][lane * 4 + 1] = v.y;
        tile[wid][lane * 4 + 2] = v.z;
        tile[wid][lane * 4 + 3] = v.w;
        __syncthreads();
        int r = tid >> 3;
        int cc = (tid & 7) * 4;
        float4 o;
        o.x = tile[cc + 0][r];
        o.y = tile[cc + 1][r];
        o.z = tile[cc + 2][r];
        o.w = tile[cc + 3][r];
        *(float4*)(g_pT + (size_t)(ty * 128 + r) * C + tx * 32 + cc) = o;
        return;
    }
    if (blk < 224) {
        int j = (blk - 192) * 32 + wid;
        const float* pr = p + (size_t)j * D;
        float ss = 0.f;
#pragma unroll
        for (int t = 0; t < 24; t++) { float v = pr[lane + 32 * t]; ss += v * v; }
#pragma unroll
        for (int d = 16; d > 0; d >>= 1) ss += __shfl_xor_sync(0xFFFFFFFFu, ss, d);
        if (lane == 0) g_pinv[j] = 1.f / fmaxf(sqrtf(ss), 1e-12f);
        return;
    }

    // ---- dtype probe on this batch's word window [b*1024, b*1024+1024) ----
    int b = (blk < 240) ? (blk - 224) : (blk - 240);
    int w0 = tg[b * 1024 + tid];                       // word view; in-bounds either dtype
    bool oddnz = ((tid & 1) != 0) && (w0 != 0);
    unsigned ob = __ballot_sync(0xFFFFFFFFu, oddnz);
    if (lane == 0) wtot[wid] = ob ? 1u : 0u;
    __syncthreads();
    if (tid == 0) {
        unsigned fl = 0;
        for (int w = 0; w < 32; w++) fl |= wtot[w];
        s_ts = fl ? 1 : 2;                             // 1=int32, 2=int64
    }
    __syncthreads();
    int ts = s_ts;
    bool posc = (ts == 1) ? (w0 != 0) : (tg[(b * C + tid) * 2] != 0);
    __syncthreads();

    if (blk < 240) {
        // ---- rand-negative membership + mask byte ----
        float r = rs[b * C + tid];
        unsigned key = posc ? 0u : (__float_as_uint(r) + 1u);   // monotone, >0

        radix_select_desc(key, KR, hist, S, wtot, &sh_prefix, &sh_rem, tid, lane);
        unsigned T = sh_prefix;
        unsigned remf = sh_rem;

        // tie resolution by lowest index (matches jax.lax.top_k stability)
        bool eq = (key == T) && (key != 0u);
        unsigned eb = __ballot_sync(0xFFFFFFFFu, eq);
        if (lane == 0) wtot[wid] = (unsigned)__popc(eb);
        __syncthreads();
        unsigned off = 0;
        for (int w = 0; w < wid; w++) off += wtot[w];
        unsigned rank = off + (unsigned)__popc(eb & ((1u << lane) - 1u));
        bool in = (key != 0u) && ((key > T) || (eq && rank < remf));
        g_mask[b * C + tid] = (unsigned char)((posc ? 2 : 0) | (in ? 1 : 0));
    } else {
        // ---- rank-based compaction ----
        unsigned bal = __ballot_sync(0xFFFFFFFFu, posc);
        if (lane == 0) wtot[wid] = (unsigned)__popc(bal);
        __syncthreads();
        unsigned off = 0;
        for (int w = 0; w < wid; w++) off += wtot[w];
        unsigned rank = off + (unsigned)__popc(bal & ((1u << lane) - 1u));
        if (posc) g_list[b * 1024 + rank] = tid;
        if (tid == 0) {
            unsigned cnt = 0;
            for (int w = 0; w < 32; w++) cnt += wtot[w];
            g_cnt[b] = (int)cnt;
            g_poscnt[b] = (float)(cnt > 0 ? cnt : 1u);
            if (b == 0) g_done = 0u;                   // reset tail counter each launch
        }
    }
}

// ===========================================================================
// GEMM: items = (anchor group of GG) x (k-quarter). 256 threads, 4 cols/thread,
// f rows pre-duplicated {v,v} in smem, inner loop = LDS.64-bcast + FFMA2.
// 18.4 KB smem -> 2 co-resident blocks/SM (4 warps/SMSP) for latency hiding.
__global__ void __launch_bounds__(256) k_gemm(const float* __restrict__ f) {
    __shared__ unsigned long long f2_s[GG][KQ];   // 18,432 B
    __shared__ int s_anchor[GG];
    __shared__ int s_pfx[17];

    int tid = threadIdx.x;
    int wid = tid >> 5, lane = tid & 31;

    if (tid == 0) {
        int acc = 0;
        for (int b = 0; b < B; b++) { s_pfx[b] = acc; acc += g_cnt[b]; }
        s_pfx[16] = acc;
    }
    __syncthreads();
    int npos = s_pfx[16];
    int ng = (npos + GG - 1) / GG;
    int nitems = ng * KSPLIT;

    for (int item = blockIdx.x; item < nitems; item += GEMM_BLOCKS) {
        int grp = item >> 2;
        int quarter = item & 3;
        __syncthreads();   // previous iter's f2_s reads done
        if (tid < GG) {
            int idx = grp * GG + tid;
            int aa = -1;
            if (idx < npos) {
                int bb = 0;
                while (bb < 15 && idx >= s_pfx[bb + 1]) bb++;
                aa = bb * C + g_list[bb * 1024 + (idx - s_pfx[bb])];
            }
            s_anchor[tid] = aa;
        }
        __syncthreads();

        for (int u = wid; u < GG; u += 8) {
            int a = s_anchor[u];
            float vs[24];
            float ss = 0.f;
            if (a >= 0) {
                const float* fr = f + (size_t)a * D;
#pragma unroll
                for (int t = 0; t < 24; t++) {
                    float v = fr[lane + 32 * t];
                    vs[t] = v; ss += v * v;
                }
            } else {
#pragma unroll
                for (int t = 0; t < 24; t++) vs[t] = 0.f;
            }
#pragma unroll
            for (int d = 16; d > 0; d >>= 1) ss += __shfl_xor_sync(0xFFFFFFFFu, ss, d);
            float inv = (1.f / fmaxf(sqrtf(ss), 1e-12f)) * (1.f / TAUF);
#pragma unroll
            for (int t = 0; t < 6; t++) {
                unsigned vb = __float_as_uint(vs[quarter * 6 + t] * inv);
                f2_s[u][lane + 32 * t] = ((unsigned long long)vb << 32) | vb;
            }
        }
        __syncthreads();

        int col = 4 * tid;
        const float* pc = g_pT + (size_t)quarter * KQ * C + col;
        unsigned long long accA[GG], accB[GG];
#pragma unroll
        for (int u = 0; u < GG; u++) { accA[u] = 0ull; accB[u] = 0ull; }

#pragma unroll 4
        for (int k = 0; k < KQ; k++) {
            union { float4 v; unsigned long long ll[2]; } pu;
            pu.v = *(const float4*)(pc + (size_t)k * C);
#pragma unroll
            for (int u = 0; u < GG; u++) {
                unsigned long long fv = f2_s[u][k];
                accA[u] = ffma2(fv, pu.ll[0], accA[u]);
                accB[u] = ffma2(fv, pu.ll[1], accB[u]);
            }
        }

        float4 pinv = *(const float4*)(g_pinv + col);
        int base = grp * GG;
#pragma unroll
        for (int u = 0; u < GG; u++) {
            if (base + u < npos) {
                float2 a2 = *(float2*)&accA[u];
                float2 b2 = *(float2*)&accB[u];
                float4 o;
                o.x = a2.x * pinv.x; o.y = a2.y * pinv.y;
                o.z = b2.x * pinv.z; o.w = b2.y * pinv.w;
                *(float4*)&g_sims[(size_t)(base + u) * (KSPLIT * 1024) +
                                  quarter * 1024 + col] = o;
            }
        }
    }
}

// ===========================================================================
// select+loss+final: 4 independent 256-thread groups per block; per-anchor
// radix select; losses stored pre-divided by poscnt; last block to finish
// performs the flat deterministic sum and writes the scalar output.
__global__ void __launch_bounds__(1024) k_select(float* __restrict__ out) {
    __shared__ unsigned hist[4][256];
    __shared__ unsigned S[4][256];
    __shared__ unsigned wtot[4][8];
    __shared__ unsigned sh_prefix[4], sh_rem[4];
    __shared__ unsigned u_red[4][8];
    __shared__ float    f_red[4][8];
    __shared__ float    s_vT[4], s_possim[4];
    __shared__ int      s_pfx[17];
    __shared__ int      s_last;
    __shared__ float    s_fin[32];

    int tid = threadIdx.x;
    int lane = tid & 31;
    int g = tid >> 8;            // group 0..3
    int gtid = tid & 255;
    int wg = (tid >> 5) & 7;     // warp within group
    int barid = g + 1;

    if (tid == 0) {
        int acc = 0;
        for (int b = 0; b < B; b++) { s_pfx[b] = acc; acc += g_cnt[b]; }
        s_pfx[16] = acc;
    }
    __syncthreads();
    int npos = s_pfx[16];

    for (int i = blockIdx.x * 4 + g; i < npos; i += SEL_BLOCKS * 4) {
        // anchor decode (redundant per thread; no sync needed)
        int bb = 0;
        while (bb < 15 && i >= s_pfx[bb + 1]) bb++;
        int c = g_list[bb * 1024 + (i - s_pfx[bb])];

        // load 4 partials per column, fixed summation order
        const float* sp = g_sims + (size_t)i * (KSPLIT * 1024) + 4 * gtid;
        float4 q0 = *(const float4*)(sp);
        float4 q1 = *(const float4*)(sp + 1024);
        float4 q2 = *(const float4*)(sp + 2048);
        float4 q3 = *(const float4*)(sp + 3072);
        float sim[4];
        sim[0] = (q0.x + q1.x) + (q2.x + q3.x);
        sim[1] = (q0.y + q1.y) + (q2.y + q3.y);
        sim[2] = (q0.z + q1.z) + (q2.z + q3.z);
        sim[3] = (q0.w + q1.w) + (q2.w + q3.w);

        uchar4 mk4 = *(const uchar4*)(g_mask + bb * C + 4 * gtid);
        unsigned char mk[4] = {mk4.x, mk4.y, mk4.z, mk4.w};

        unsigned key[4];
#pragma unroll
        for (int x = 0; x < 4; x++) {
            unsigned bits = __float_as_uint(sim[x]);
            unsigned flip = bits ^ ((bits & 0x80000000u) ? 0xFFFFFFFFu : 0x80000000u);
            key[x] = (mk[x] & 2) ? 0u : flip;
        }
        if ((c >> 2) == gtid) s_possim[g] = sim[c & 3];

        // max negative key -> m
        unsigned mx = max(max(key[0], key[1]), max(key[2], key[3]));
#pragma unroll
        for (int d = 16; d > 0; d >>= 1) mx = max(mx, __shfl_xor_sync(0xFFFFFFFFu, mx, d));
        if (lane == 0) u_red[g][wg] = mx;
        gbar(barid);
        unsigned maxkey = u_red[g][0];
#pragma unroll
        for (int w = 1; w < 8; w++) maxkey = max(maxkey, u_red[g][w]);
        unsigned mbits = (maxkey & 0x80000000u) ? (maxkey ^ 0x80000000u) : ~maxkey;
        float m = __uint_as_float(mbits);

        radix4(key, KH, hist[g], S[g], wtot[g], &sh_prefix[g], &sh_rem[g],
               gtid, lane, wg, barid);
        unsigned T = sh_prefix[g];
        unsigned remf = sh_rem[g];

        float contrib = 0.f;
#pragma unroll
        for (int x = 0; x < 4; x++) {
            float e = expf(sim[x] - m);
            if (key[x] > T) contrib += e;
            if (key[x] == T && key[x] != 0u) s_vT[g] = sim[x];  // equal keys = equal values
            if (mk[x] & 1) contrib += e;
        }
#pragma unroll
        for (int d = 16; d > 0; d >>= 1) contrib += __shfl_xor_sync(0xFFFFFFFFu, contrib, d);
        if (lane == 0) f_red[g][wg] = contrib;
        gbar(barid);
        if (gtid == 0) {
            float tot = 0.f;
            for (int w = 0; w < 8; w++) tot += f_red[g][w];
            tot += (float)remf * expf(s_vT[g] - m);
            float lse = m + logf(tot);
            float x = lse - s_possim[g];
            float loss = fmaxf(x, 0.f) + log1pf(expf(-fabsf(x)));
            g_lossd[i] = loss / g_poscnt[bb];          // pre-normalized
        }
        gbar(barid);   // close iteration: protect s_possim / s_vT / smem reuse
    }

    // ---- fused final reduction: last block to arrive sums everything ----
    __syncthreads();
    if (tid == 0) {
        __threadfence();
        unsigned r = atomicAdd(&g_done, 1u);
        s_last = (r == SEL_BLOCKS - 1) ? 1 : 0;
    }
    __syncthreads();
    if (s_last) {
        float ps = 0.f;
        for (int j = tid; j < npos; j += 1024) ps += g_lossd[j];
#pragma unroll
        for (int d = 16; d > 0; d >>= 1) ps += __shfl_xor_sync(0xFFFFFFFFu, ps, d);
        if (lane == 0) s_fin[tid >> 5] = ps;
        __syncthreads();
        if (tid < 32) {
            float t = s_fin[tid];
#pragma unroll
            for (int d = 16; d > 0; d >>= 1) t += __shfl_xor_sync(0xFFFFFFFFu, t, d);
            if (tid == 0) out[0] = t / (float)B;
        }
    }
}

// ===========================================================================
extern "C" void kernel_launch(void* const* d_in, const int* in_sizes, int n_in,
                              void* d_out, int out_size) {
    const float* f  = (const float*)d_in[0];   // (B,C,D) fp32
    const float* p  = (const float*)d_in[1];   // (C,D)   fp32
    const int*   tg = (const int*)d_in[2];     // (B,C)   int32 (or int64; self-probed)
    const float* rs = (const float*)d_in[3];   // (B,C)   fp32
    float* out = (float*)d_out;

    k_prep<<<256, 1024>>>(p, tg, rs);
    k_gemm<<<GEMM_BLOCKS, 256>>>(f);
    k_select<<<SEL_BLOCKS, 1024>>>(out);
}